// round 1
// baseline (speedup 1.0000x reference)
#include <cuda_runtime.h>
#include <math.h>

#define H     768
#define BSZ   8
#define TLEN  64
#define ILEN  197
#define NHEADS 12
#define DH    64

// ---------------- device scratch (no allocations allowed) ----------------
__device__ float g_text_emb[BSZ*TLEN*H];
__device__ float g_q       [BSZ*TLEN*H];
__device__ float g_image_emb[BSZ*ILEN*H];
__device__ float g_k       [BSZ*ILEN*H];
__device__ float g_v       [BSZ*ILEN*H];
__device__ float g_kT      [BSZ*NHEADS*DH*ILEN];
__device__ float g_gate    [BSZ*TLEN*ILEN];

// ---------------- generic projection GEMM: C = A @ W + bias ----------------
// A[M,768] row-major, W[768,768] row-major, C selected by which_out.
// Tiles: BM=64, BN=64, BK=16, 256 threads, 4x4 per-thread.
__global__ __launch_bounds__(256)
void gemm_bias_kernel(const float* __restrict__ A,
                      const float* __restrict__ W,
                      const float* __restrict__ bias,
                      int M, int which_out) {
    float* C = (which_out == 0) ? g_text_emb :
               (which_out == 1) ? g_q :
               (which_out == 2) ? g_image_emb :
               (which_out == 3) ? g_k : g_v;

    __shared__ __align__(16) float As[64][17];
    __shared__ __align__(16) float Ws[16][64];

    const int tid = threadIdx.x;
    const int tx = tid & 15, ty = tid >> 4;
    const int row0 = blockIdx.y * 64, col0 = blockIdx.x * 64;

    float acc[4][4] = {};

    for (int k0 = 0; k0 < H; k0 += 16) {
        {
            int r = tid >> 2;
            int c = (tid & 3) << 2;
            int gr = row0 + r;
            float4 av = (gr < M) ? *(const float4*)(A + gr*H + k0 + c)
                                 : make_float4(0.f,0.f,0.f,0.f);
            As[r][c] = av.x; As[r][c+1] = av.y; As[r][c+2] = av.z; As[r][c+3] = av.w;
            int r2 = tid >> 4, c2 = (tid & 15) << 2;
            *(float4*)&Ws[r2][c2] = *(const float4*)(W + (k0 + r2)*H + col0 + c2);
        }
        __syncthreads();
        #pragma unroll
        for (int kk = 0; kk < 16; ++kk) {
            float a[4], w[4];
            #pragma unroll
            for (int i = 0; i < 4; i++) a[i] = As[ty*4 + i][kk];
            #pragma unroll
            for (int j = 0; j < 4; j++) w[j] = Ws[kk][tx*4 + j];
            #pragma unroll
            for (int i = 0; i < 4; i++)
                #pragma unroll
                for (int j = 0; j < 4; j++) acc[i][j] += a[i] * w[j];
        }
        __syncthreads();
    }

    #pragma unroll
    for (int i = 0; i < 4; i++) {
        int gr = row0 + ty*4 + i;
        if (gr < M) {
            #pragma unroll
            for (int j = 0; j < 4; j++)
                C[gr*H + col0 + tx*4 + j] = acc[i][j] + bias[col0 + tx*4 + j];
        }
    }
}

// ---------------- gate kernel ----------------
// For each (b, t0..t0+7, i0..i0+3): rel row = te[t] * ie[i]; hidden = relu(rel@W1+b1);
// gate = sigmoid(hidden . W2 + b2). Never materializes rel/hidden to gmem.
// Block C-tile: 32 rel-rows (8t x 4i) x 128 cols, N looped in 6 tiles; 256 threads.
// Thread tile: 2 rows x 8 cols (as two float4 halves at +0 and +64), packed f32x2 FMA.
__global__ __launch_bounds__(256)
void gate_kernel(const float* __restrict__ W1,
                 const float* __restrict__ b1,
                 const float* __restrict__ W2,
                 const float* __restrict__ b2) {
    __shared__ __align__(16) float s_te[8][H];      // 24 KB
    __shared__ __align__(16) float s_ie[4][H];      // 12 KB
    __shared__ __align__(16) float s_w1[16][128];   //  8 KB

    const int tid = threadIdx.x;
    const int tc = tid & 15;     // column group 0..15
    const int tr = tid >> 4;     // row pair   0..15
    const int b  = blockIdx.z;
    const int t0 = blockIdx.y * 8;
    const int i0 = blockIdx.x * 4;

    // stage te rows (8 x 768) and ie rows (4 x 768, zero-fill OOB)
    {
        const float* te = g_text_emb + (b*TLEN + t0) * H;
        for (int idx = tid; idx < 8*(H/4); idx += 256) {
            int r = idx / (H/4), c4 = (idx % (H/4)) << 2;
            *(float4*)&s_te[r][c4] = *(const float4*)(te + r*H + c4);
        }
        for (int idx = tid; idx < 4*(H/4); idx += 256) {
            int r = idx / (H/4), c4 = (idx % (H/4)) << 2;
            int gi = i0 + r;
            float4 v = (gi < ILEN) ? *(const float4*)(g_image_emb + (b*ILEN + gi)*H + c4)
                                   : make_float4(0.f,0.f,0.f,0.f);
            *(float4*)&s_ie[r][c4] = v;
        }
    }

    // row mapping: rel-row r = t_l*4 + i_l; this thread owns rows 2*tr, 2*tr+1
    const int t_l  = tr >> 1;
    const int i_l0 = (tr & 1) * 2;
    const int i_l1 = i_l0 + 1;

    float gacc0 = 0.f, gacc1 = 0.f;

    for (int nt = 0; nt < H/128; ++nt) {   // 6 N-tiles
        const int n0 = nt * 128;
        unsigned long long acc[8];
        #pragma unroll
        for (int q = 0; q < 8; q++) acc[q] = 0ull;

        for (int k0 = 0; k0 < H; k0 += 16) {
            __syncthreads();   // protect s_w1 (also covers initial te/ie staging)
            #pragma unroll
            for (int q = 0; q < 2; q++) {
                int idx = tid + q*256;
                int kr = idx >> 5, c4 = (idx & 31) << 2;
                *(float4*)&s_w1[kr][c4] = *(const float4*)(W1 + (k0 + kr)*H + n0 + c4);
            }
            __syncthreads();

            // rel values for this k-chunk (te row shared by both rel rows)
            float rel0[16], rel1[16];
            #pragma unroll
            for (int kk = 0; kk < 16; kk += 4) {
                float4 tv = *(const float4*)&s_te[t_l ][k0 + kk];
                float4 e0 = *(const float4*)&s_ie[i_l0][k0 + kk];
                float4 e1 = *(const float4*)&s_ie[i_l1][k0 + kk];
                rel0[kk+0] = tv.x*e0.x; rel0[kk+1] = tv.y*e0.y;
                rel0[kk+2] = tv.z*e0.z; rel0[kk+3] = tv.w*e0.w;
                rel1[kk+0] = tv.x*e1.x; rel1[kk+1] = tv.y*e1.y;
                rel1[kk+2] = tv.z*e1.z; rel1[kk+3] = tv.w*e1.w;
            }

            #pragma unroll
            for (int kk = 0; kk < 16; ++kk) {
                const unsigned long long* wrow = (const unsigned long long*)&s_w1[kk][0];
                unsigned long long wa0 = wrow[tc*2];
                unsigned long long wa1 = wrow[tc*2 + 1];
                unsigned long long wb0 = wrow[32 + tc*2];
                unsigned long long wb1 = wrow[32 + tc*2 + 1];
                unsigned long long rp0, rp1;
                asm("mov.b64 %0, {%1, %1};" : "=l"(rp0) : "f"(rel0[kk]));
                asm("mov.b64 %0, {%1, %1};" : "=l"(rp1) : "f"(rel1[kk]));
                asm("fma.rn.f32x2 %0, %1, %2, %0;" : "+l"(acc[0]) : "l"(wa0), "l"(rp0));
                asm("fma.rn.f32x2 %0, %1, %2, %0;" : "+l"(acc[1]) : "l"(wa1), "l"(rp0));
                asm("fma.rn.f32x2 %0, %1, %2, %0;" : "+l"(acc[2]) : "l"(wb0), "l"(rp0));
                asm("fma.rn.f32x2 %0, %1, %2, %0;" : "+l"(acc[3]) : "l"(wb1), "l"(rp0));
                asm("fma.rn.f32x2 %0, %1, %2, %0;" : "+l"(acc[4]) : "l"(wa0), "l"(rp1));
                asm("fma.rn.f32x2 %0, %1, %2, %0;" : "+l"(acc[5]) : "l"(wa1), "l"(rp1));
                asm("fma.rn.f32x2 %0, %1, %2, %0;" : "+l"(acc[6]) : "l"(wb0), "l"(rp1));
                asm("fma.rn.f32x2 %0, %1, %2, %0;" : "+l"(acc[7]) : "l"(wb1), "l"(rp1));
            }
        }

        // epilogue: +b1, relu, dot with W2 -> per-row scalar
        const int cA = n0 + tc*4;
        const int cB = n0 + 64 + tc*4;
        #pragma unroll
        for (int q = 0; q < 8; ++q) {
            int qq = q & 3;
            int c = ((qq < 2) ? cA : cB) + (qq & 1)*2;
            float lo, hi;
            asm("mov.b64 {%0, %1}, %2;" : "=f"(lo), "=f"(hi) : "l"(acc[q]));
            float h0 = fmaxf(lo + b1[c  ], 0.f) * W2[c  ];
            float h1 = fmaxf(hi + b1[c+1], 0.f) * W2[c+1];
            if (q < 4) gacc0 += h0 + h1; else gacc1 += h0 + h1;
        }
    }

    // reduce across the 16 column-group threads (contiguous 16-lane segments)
    #pragma unroll
    for (int off = 8; off; off >>= 1) {
        gacc0 += __shfl_xor_sync(0xffffffffu, gacc0, off, 16);
        gacc1 += __shfl_xor_sync(0xffffffffu, gacc1, off, 16);
    }

    if (tc == 0) {
        int t  = t0 + t_l;
        int ia = i0 + i_l0;
        int ib = i0 + i_l1;
        float bb = b2[0];
        if (ia < ILEN)
            g_gate[(b*TLEN + t)*ILEN + ia] = 1.f / (1.f + expf(-(gacc0 + bb)));
        if (ib < ILEN)
            g_gate[(b*TLEN + t)*ILEN + ib] = 1.f / (1.f + expf(-(gacc1 + bb)));
    }
}

// ---------------- repack k -> kT[b][h][d][i] for coalesced score loads ----------------
__global__ __launch_bounds__(256)
void repack_kT_kernel() {
    int idx = blockIdx.x * 256 + threadIdx.x;
    const int total = BSZ*NHEADS*DH*ILEN;
    if (idx >= total) return;
    int i = idx % ILEN;
    int d = (idx / ILEN) % DH;
    int h = (idx / (ILEN*DH)) % NHEADS;
    int b = idx / (ILEN*DH*NHEADS);
    g_kT[idx] = g_k[(b*ILEN + i)*H + h*DH + d];
}

// ---------------- attention: scores -> softmax -> *gate -> ctx ----------------
// grid (t_tiles=8, h=12, b=8), 256 threads = 8 warps, each warp owns one t row.
__global__ __launch_bounds__(256)
void attn_kernel(float* __restrict__ out) {
    __shared__ float q_s[8][DH];
    __shared__ float p_s[8][ILEN + 3];

    const int w    = threadIdx.x >> 5;
    const int lane = threadIdx.x & 31;
    const int b = blockIdx.z, h = blockIdx.y;
    const int t = blockIdx.x * 8 + w;

    const float* qrow = g_q + (b*TLEN + t)*H + h*DH;
    q_s[w][lane]      = qrow[lane];
    q_s[w][lane + 32] = qrow[lane + 32];
    __syncwarp();

    const float* kT = g_kT + (b*NHEADS + h) * DH * ILEN;
    const float scale = 0.125f;   // 1/sqrt(64)

    float mx = -1e30f;
    for (int c = 0; c < 7; ++c) {
        int i = c*32 + lane;
        float s = -1e30f;
        if (i < ILEN) {
            float a0 = 0.f, a1 = 0.f, a2 = 0.f, a3 = 0.f;
            #pragma unroll
            for (int d = 0; d < DH; d += 4) {
                a0 += q_s[w][d+0] * kT[(d+0)*ILEN + i];
                a1 += q_s[w][d+1] * kT[(d+1)*ILEN + i];
                a2 += q_s[w][d+2] * kT[(d+2)*ILEN + i];
                a3 += q_s[w][d+3] * kT[(d+3)*ILEN + i];
            }
            s = (a0 + a1 + a2 + a3) * scale;
            p_s[w][i] = s;
        }
        mx = fmaxf(mx, s);
    }
    #pragma unroll
    for (int off = 16; off; off >>= 1)
        mx = fmaxf(mx, __shfl_xor_sync(0xffffffffu, mx, off));

    float sm = 0.f;
    for (int c = 0; c < 7; ++c) {
        int i = c*32 + lane;
        if (i < ILEN) {
            float e = expf(p_s[w][i] - mx);
            p_s[w][i] = e;
            sm += e;
        }
    }
    #pragma unroll
    for (int off = 16; off; off >>= 1)
        sm += __shfl_xor_sync(0xffffffffu, sm, off);
    float inv = 1.f / sm;

    const float* gaterow = g_gate + (b*TLEN + t)*ILEN;
    for (int c = 0; c < 7; ++c) {
        int i = c*32 + lane;
        if (i < ILEN) p_s[w][i] *= inv * gaterow[i];
    }
    __syncwarp();

    float c0 = 0.f, c1 = 0.f;
    const float* vbase = g_v + b*ILEN*H + h*DH;
    for (int i = 0; i < ILEN; ++i) {
        float p = p_s[w][i];
        c0 += p * vbase[i*H + lane];
        c1 += p * vbase[i*H + lane + 32];
    }
    float* orow = out + (b*TLEN + t)*H + h*DH;
    orow[lane]      = c0;
    orow[lane + 32] = c1;
}

// ---------------- launch ----------------
extern "C" void kernel_launch(void* const* d_in, const int* in_sizes, int n_in,
                              void* d_out, int out_size) {
    const float* text  = (const float*)d_in[0];
    const float* image = (const float*)d_in[1];
    const float* Wq = (const float*)d_in[2];  const float* bq = (const float*)d_in[3];
    const float* Wk = (const float*)d_in[4];  const float* bk = (const float*)d_in[5];
    const float* Wv = (const float*)d_in[6];  const float* bv = (const float*)d_in[7];
    const float* Wt = (const float*)d_in[8];  const float* bt = (const float*)d_in[9];
    const float* Wi = (const float*)d_in[10]; const float* bi = (const float*)d_in[11];
    const float* W1 = (const float*)d_in[12]; const float* b1 = (const float*)d_in[13];
    const float* W2 = (const float*)d_in[14]; const float* b2 = (const float*)d_in[15];
    float* out = (float*)d_out;

    dim3 gt(H/64, (BSZ*TLEN + 63)/64);   // 12 x 8
    dim3 gi(H/64, (BSZ*ILEN + 63)/64);   // 12 x 25
    gemm_bias_kernel<<<gt, 256>>>(text,  Wt, bt, BSZ*TLEN, 0);
    gemm_bias_kernel<<<gt, 256>>>(text,  Wq, bq, BSZ*TLEN, 1);
    gemm_bias_kernel<<<gi, 256>>>(image, Wi, bi, BSZ*ILEN, 2);
    gemm_bias_kernel<<<gi, 256>>>(image, Wk, bk, BSZ*ILEN, 3);
    gemm_bias_kernel<<<gi, 256>>>(image, Wv, bv, BSZ*ILEN, 4);

    repack_kT_kernel<<<(BSZ*NHEADS*DH*ILEN + 255)/256, 256>>>();

    gate_kernel<<<dim3((ILEN + 3)/4, TLEN/8, BSZ), 256>>>(W1, b1, W2, b2);

    attn_kernel<<<dim3(TLEN/8, NHEADS, BSZ), 256>>>(out);
}

// round 5
// speedup vs baseline: 9.2132x; 9.2132x over previous
#include <cuda_runtime.h>
#include <cuda_fp16.h>
#include <cstdint>
#include <math.h>

#define H     768
#define BSZ   8
#define TLEN  64
#define ILEN  197
#define NHEADS 12
#define DH    64

// ---------------- device scratch (no allocations allowed) ----------------
__device__ float g_text_emb[BSZ*TLEN*H];
__device__ float g_q       [BSZ*TLEN*H];
__device__ float g_image_emb[BSZ*ILEN*H];
__device__ float g_k       [BSZ*ILEN*H];
__device__ float g_v       [BSZ*ILEN*H];
__device__ float g_kT      [BSZ*NHEADS*DH*ILEN];
__device__ float g_gate    [BSZ*TLEN*ILEN];
__device__ __half g_WTh[6*H*H];   // W^T hi halves: Wt,Wq,Wi,Wk,Wv,W1
__device__ __half g_WTl[6*H*H];   // W^T lo residual halves

// ---------------- asm helpers (all base-sm_100-legal: sm_75/80 era) ----------------
__device__ __forceinline__ uint32_t smem_u32(const void* p) {
    uint32_t a;
    asm("{ .reg .u64 t; cvta.to.shared.u64 t, %1; cvt.u32.u64 %0, t; }" : "=r"(a) : "l"(p));
    return a;
}
__device__ __forceinline__ void ldm_x4(uint32_t* r, uint32_t addr) {
    asm volatile("ldmatrix.sync.aligned.m8n8.x4.shared.b16 {%0,%1,%2,%3}, [%4];"
        : "=r"(r[0]), "=r"(r[1]), "=r"(r[2]), "=r"(r[3]) : "r"(addr));
}
__device__ __forceinline__ void ldm_x2(uint32_t* r, uint32_t addr) {
    asm volatile("ldmatrix.sync.aligned.m8n8.x2.shared.b16 {%0,%1}, [%2];"
        : "=r"(r[0]), "=r"(r[1]) : "r"(addr));
}
__device__ __forceinline__ void mma16816(float* c, const uint32_t* a, const uint32_t* b) {
    asm volatile("mma.sync.aligned.m16n8k16.row.col.f32.f16.f16.f32 "
        "{%0,%1,%2,%3}, {%4,%5,%6,%7}, {%8,%9}, {%0,%1,%2,%3};"
        : "+f"(c[0]), "+f"(c[1]), "+f"(c[2]), "+f"(c[3])
        : "r"(a[0]), "r"(a[1]), "r"(a[2]), "r"(a[3]), "r"(b[0]), "r"(b[1]));
}
__device__ __forceinline__ uint32_t hm2(uint32_t a, uint32_t b) {
    uint32_t r; asm("mul.f16x2 %0, %1, %2;" : "=r"(r) : "r"(a), "r"(b)); return r;
}
__device__ __forceinline__ uint32_t h2bits(__half2 h) { return *reinterpret_cast<uint32_t*>(&h); }
#define CPA(dst, src) asm volatile("cp.async.cg.shared.global [%0], [%1], 16;" :: "r"(dst), "l"(src))
#define CPC() asm volatile("cp.async.commit_group;" ::: "memory")
#define CPW0() asm volatile("cp.async.wait_group 0;" ::: "memory")

// ---------------- prep: transpose weights, split into hi/lo halves ----------------
__global__ __launch_bounds__(256)
void prep_weights(const float* __restrict__ Wt, const float* __restrict__ Wq,
                  const float* __restrict__ Wi, const float* __restrict__ Wk,
                  const float* __restrict__ Wv, const float* __restrict__ W1) {
    __shared__ float ts[32][33];
    const float* in = (blockIdx.z == 0) ? Wt : (blockIdx.z == 1) ? Wq :
                      (blockIdx.z == 2) ? Wi : (blockIdx.z == 3) ? Wk :
                      (blockIdx.z == 4) ? Wv : W1;
    __half* oh = g_WTh + (size_t)blockIdx.z * H * H;
    __half* ol = g_WTl + (size_t)blockIdx.z * H * H;
    int x0 = blockIdx.x * 32, y0 = blockIdx.y * 32;
    int tx = threadIdx.x & 31, ty = threadIdx.x >> 5;
    #pragma unroll
    for (int j = 0; j < 32; j += 8)
        ts[ty + j][tx] = in[(y0 + ty + j) * H + x0 + tx];
    __syncthreads();
    #pragma unroll
    for (int j = 0; j < 32; j += 8) {
        float v = ts[tx][ty + j];
        __half h = __float2half_rn(v);
        __half l = __float2half_rn(v - __half2float(h));
        int o = (x0 + ty + j) * H + y0 + tx;
        oh[o] = h;
        ol[o] = l;
    }
}

// ============================================================================
// Projection GEMM via split-fp16 mma.sync: C = A @ W + bias (fp32-grade)
// grid (6 ntiles, 13 mtiles, 5 gemms), 256 threads (8 warps: 2M x 4N),
// M-tile 128, N-tile 128, warp tile 64x32, K chunks of 64 halves.
// SMEM buffers (16KB each, double-buffered): Ah, Al, Bh, Bl.
// ============================================================================
#define PJ_AH 0
#define PJ_AL 32768
#define PJ_BH 65536
#define PJ_BL 98304
#define PJ_SMEM 131072

__device__ __forceinline__ void pj_fill_b(uint32_t sb, size_t wofs,
                                          int n0, int k0, int buf, int tid) {
    int row = tid >> 1;                // 0..127 (n rows)
    int c0  = (tid & 1) * 4;           // 4 chunks of 8 halves each
    size_t src = wofs + (size_t)(n0 + row) * H + k0;
    uint32_t dh = sb + PJ_BH + buf * 16384 + row * 128;
    uint32_t dl = sb + PJ_BL + buf * 16384 + row * 128;
    #pragma unroll
    for (int q = 0; q < 4; ++q) {
        int cidx = c0 + q;
        uint32_t sw = (uint32_t)((cidx ^ (row & 7)) << 4);
        CPA(dh + sw, g_WTh + src + cidx * 8);
        CPA(dl + sw, g_WTl + src + cidx * 8);
    }
    CPC();
}

__global__ __launch_bounds__(256)
void proj_kernel(const float* __restrict__ text, const float* __restrict__ image,
                 const float* __restrict__ bt, const float* __restrict__ bq,
                 const float* __restrict__ bi, const float* __restrict__ bk,
                 const float* __restrict__ bv) {
    const int z = blockIdx.z;
    const int M = (z < 2) ? BSZ * TLEN : BSZ * ILEN;
    const int m0 = blockIdx.y * 128;
    if (m0 >= M) return;
    const int n0 = blockIdx.x * 128;

    const float* A = (z < 2) ? text : image;
    const size_t wofs = (size_t)z * H * H;
    const float* bias = (z == 0) ? bt : (z == 1) ? bq : (z == 2) ? bi : (z == 3) ? bk : bv;
    float* C = (z == 0) ? g_text_emb : (z == 1) ? g_q :
               (z == 2) ? g_image_emb : (z == 3) ? g_k : g_v;

    extern __shared__ char smem[];
    const uint32_t sb = smem_u32(smem);
    const int tid = threadIdx.x;
    const int wid = tid >> 5, lane = tid & 31;
    const int warp_m = wid & 1, warp_n = wid >> 1;

    float acc[64];
    #pragma unroll
    for (int q = 0; q < 64; ++q) acc[q] = 0.f;

    // pre-issue B stage 0
    pj_fill_b(sb, wofs, n0, 0, 0, tid);

    for (int kc = 0; kc < 12; ++kc) {
        const int buf = kc & 1;
        const int k0 = kc * 64;

        // build A hi/lo tile: 128 rows x 64 halves (2 threads per row)
        {
            int row = tid >> 1, hs = tid & 1;
            int grow = m0 + row;
            bool valid = grow < M;
            const float* src = A + (size_t)grow * H + k0 + hs * 32;
            char* ah = smem + PJ_AH + buf * 16384 + row * 128;
            char* al = smem + PJ_AL + buf * 16384 + row * 128;
            #pragma unroll
            for (int q = 0; q < 4; ++q) {
                int cidx = hs * 4 + q;
                float4 v0 = valid ? *(const float4*)(src + q * 8)
                                  : make_float4(0.f, 0.f, 0.f, 0.f);
                float4 v1 = valid ? *(const float4*)(src + q * 8 + 4)
                                  : make_float4(0.f, 0.f, 0.f, 0.f);
                float e[8] = {v0.x, v0.y, v0.z, v0.w, v1.x, v1.y, v1.z, v1.w};
                uint4 hv, lv;
                uint32_t* hp = &hv.x;
                uint32_t* lp = &lv.x;
                #pragma unroll
                for (int j = 0; j < 4; ++j) {
                    __half ha = __float2half_rn(e[2*j]);
                    __half hb = __float2half_rn(e[2*j+1]);
                    __half la = __float2half_rn(e[2*j]   - __half2float(ha));
                    __half lb = __float2half_rn(e[2*j+1] - __half2float(hb));
                    hp[j] = h2bits(__halves2half2(ha, hb));
                    lp[j] = h2bits(__halves2half2(la, lb));
                }
                uint32_t sw = (uint32_t)((cidx ^ (row & 7)) << 4);
                *(uint4*)(ah + sw) = hv;
                *(uint4*)(al + sw) = lv;
            }
        }
        CPW0();
        __syncthreads();
        if (kc < 11) pj_fill_b(sb, wofs, n0, (kc + 1) * 64, buf ^ 1, tid);

        // mma: 4 ksteps of 16
        const uint32_t ahb = sb + PJ_AH + buf * 16384;
        const uint32_t alb = sb + PJ_AL + buf * 16384;
        const uint32_t bhb = sb + PJ_BH + buf * 16384;
        const uint32_t blb = sb + PJ_BL + buf * 16384;
        #pragma unroll
        for (int ks = 0; ks < 4; ++ks) {
            uint32_t afh[4][4], afl[4][4];
            #pragma unroll
            for (int mi = 0; mi < 4; ++mi) {
                int rowl = warp_m * 64 + mi * 16 + (lane & 15);
                int cidx = ks * 2 + (lane >> 4);
                uint32_t off = (uint32_t)(rowl * 128 + ((cidx ^ (rowl & 7)) << 4));
                ldm_x4(afh[mi], ahb + off);
                ldm_x4(afl[mi], alb + off);
            }
            uint32_t bfh[4][2], bfl[4][2];
            #pragma unroll
            for (int ni = 0; ni < 4; ++ni) {
                int nrow = warp_n * 32 + ni * 8 + (lane & 7);
                int cidx = ks * 2 + ((lane >> 3) & 1);
                uint32_t off = (uint32_t)(nrow * 128 + ((cidx ^ (nrow & 7)) << 4));
                ldm_x2(bfh[ni], bhb + off);
                ldm_x2(bfl[ni], blb + off);
            }
            #pragma unroll
            for (int mi = 0; mi < 4; ++mi)
                #pragma unroll
                for (int ni = 0; ni < 4; ++ni) {
                    float* cc = &acc[(mi * 4 + ni) * 4];
                    mma16816(cc, afh[mi], bfh[ni]);
                    mma16816(cc, afl[mi], bfh[ni]);
                    mma16816(cc, afh[mi], bfl[ni]);
                }
        }
    }

    // epilogue: + bias, store fp32
    #pragma unroll
    for (int mi = 0; mi < 4; ++mi) {
        #pragma unroll
        for (int ni = 0; ni < 4; ++ni) {
            int r = m0 + warp_m * 64 + mi * 16 + (lane >> 2);
            int c = n0 + warp_n * 32 + ni * 8 + (lane & 3) * 2;
            float ba = __ldg(&bias[c]), bb = __ldg(&bias[c + 1]);
            const float* cc = &acc[(mi * 4 + ni) * 4];
            if (r < M)     *(float2*)(C + (size_t)r * H + c)       = make_float2(cc[0] + ba, cc[1] + bb);
            if (r + 8 < M) *(float2*)(C + (size_t)(r + 8) * H + c) = make_float2(cc[2] + ba, cc[3] + bb);
        }
    }
}

// ============================================================================
// Gate kernel: fused rel -> relu(rel@W1+b1) -> sigmoid(.@W2+b2), fp16 mma.
// grid (13 i-blocks, 4 t-blocks, 8 b), 512 threads (16 warps: 4M x 4N).
// M = 256 rel rows (16t x 16i), N looped 6 x 128, K chunks of 64.
// ============================================================================
#define GT_ZS   0
#define GT_B1   4096
#define GT_W2   7168
#define GT_TE   10240
#define GT_IE   35072
#define GT_A    59904
#define GT_B    125440
#define GT_SMEM 158208
#define TE_STR  776      // padded half stride (bank-shift rows)

__device__ __forceinline__ void gt_fill_b(uint32_t sb, const __half* W1T,
                                          int n0, int k0, int buf, int tid) {
    int row = tid >> 2;               // 0..127
    int c0  = (tid & 3) * 2;          // 2 chunks
    const __half* src = W1T + (size_t)(n0 + row) * H + k0;
    uint32_t dst = sb + GT_B + buf * 16384 + row * 128;
    #pragma unroll
    for (int q = 0; q < 2; ++q) {
        int cidx = c0 + q;
        CPA(dst + (uint32_t)((cidx ^ (row & 7)) << 4), src + cidx * 8);
    }
    CPC();
}

__global__ __launch_bounds__(512)
void gate_kernel(const float* __restrict__ b1, const float* __restrict__ W2,
                 const float* __restrict__ b2) {
    extern __shared__ char smem[];
    const uint32_t sb = smem_u32(smem);
    const int tid = threadIdx.x;
    const int wid = tid >> 5, lane = tid & 31;
    const int warp_m = wid & 3, warp_n = wid >> 2;
    const int b  = blockIdx.z;
    const int t0 = blockIdx.y * 16;
    const int i0 = blockIdx.x * 16;

    float* zs  = (float*)(smem + GT_ZS);
    float* b1s = (float*)(smem + GT_B1);
    float* w2s = (float*)(smem + GT_W2);
    __half* te = (__half*)(smem + GT_TE);
    __half* ie = (__half*)(smem + GT_IE);
    const __half* W1T = g_WTh + 5LL * H * H;

    for (int idx = tid; idx < 1024; idx += 512) zs[idx] = 0.f;
    for (int idx = tid; idx < H; idx += 512) { b1s[idx] = b1[idx]; w2s[idx] = W2[idx]; }

    // stage te/ie as halves (padded stride)
    {
        const float* teg = g_text_emb + ((size_t)b * TLEN + t0) * H;
        for (int u = tid; u < 16 * (H / 4); u += 512) {
            int r = u / (H / 4), c4 = (u % (H / 4)) * 4;
            float4 v = *(const float4*)(teg + r * H + c4);
            uint2 o;
            o.x = h2bits(__floats2half2_rn(v.x, v.y));
            o.y = h2bits(__floats2half2_rn(v.z, v.w));
            *(uint2*)((char*)te + (r * TE_STR + c4) * 2) = o;
        }
        const float* ieg = g_image_emb + (size_t)b * ILEN * H;
        for (int u = tid; u < 16 * (H / 4); u += 512) {
            int r = u / (H / 4), c4 = (u % (H / 4)) * 4;
            int gi = i0 + r;
            float4 v = (gi < ILEN) ? *(const float4*)(ieg + (size_t)gi * H + c4)
                                   : make_float4(0.f, 0.f, 0.f, 0.f);
            uint2 o;
            o.x = h2bits(__floats2half2_rn(v.x, v.y));
            o.y = h2bits(__floats2half2_rn(v.z, v.w));
            *(uint2*)((char*)ie + (r * TE_STR + c4) * 2) = o;
        }
    }
    __syncthreads();

    // pre-issue B stage 0
    gt_fill_b(sb, W1T, 0, 0, 0, tid);

    const int arow = tid >> 1, ahs = tid & 1;      // A-build mapping
    const __half* ter = te + (arow >> 4) * TE_STR;
    const __half* ier = ie + (arow & 15) * TE_STR;

    for (int nc = 0; nc < 6; ++nc) {
        const int n0 = nc * 128;
        float acc[64];
        #pragma unroll
        for (int q = 0; q < 64; ++q) acc[q] = 0.f;

        for (int kc = 0; kc < 12; ++kc) {
            const int gs = nc * 12 + kc;
            const int buf = gs & 1;
            const int k0 = kc * 64;

            // build A tile: rel = te*ie, 256 rows x 64 halves
            {
                char* ab = smem + GT_A + buf * 32768 + arow * 128;
                #pragma unroll
                for (int q = 0; q < 4; ++q) {
                    int cidx = ahs * 4 + q;
                    int k = k0 + cidx * 8;
                    uint4 t4 = *(const uint4*)((const char*)ter + k * 2);
                    uint4 i4 = *(const uint4*)((const char*)ier + k * 2);
                    uint4 p;
                    p.x = hm2(t4.x, i4.x); p.y = hm2(t4.y, i4.y);
                    p.z = hm2(t4.z, i4.z); p.w = hm2(t4.w, i4.w);
                    *(uint4*)(ab + ((cidx ^ (arow & 7)) << 4)) = p;
                }
            }
            CPW0();
            __syncthreads();
            if (gs < 71) {
                int gn = gs + 1;
                gt_fill_b(sb, W1T, (gn / 12) * 128, (gn % 12) * 64, gn & 1, tid);
            }

            const uint32_t abase = sb + GT_A + buf * 32768;
            const uint32_t bbase = sb + GT_B + buf * 16384;
            #pragma unroll
            for (int ks = 0; ks < 4; ++ks) {
                uint32_t af[4][4];
                #pragma unroll
                for (int mi = 0; mi < 4; ++mi) {
                    int rowl = warp_m * 64 + mi * 16 + (lane & 15);
                    int cidx = ks * 2 + (lane >> 4);
                    ldm_x4(af[mi], abase + (uint32_t)(rowl * 128 + ((cidx ^ (rowl & 7)) << 4)));
                }
                uint32_t bf[4][2];
                #pragma unroll
                for (int ni = 0; ni < 4; ++ni) {
                    int nrow = warp_n * 32 + ni * 8 + (lane & 7);
                    int cidx = ks * 2 + ((lane >> 3) & 1);
                    ldm_x2(bf[ni], bbase + (uint32_t)(nrow * 128 + ((cidx ^ (nrow & 7)) << 4)));
                }
                #pragma unroll
                for (int mi = 0; mi < 4; ++mi)
                    #pragma unroll
                    for (int ni = 0; ni < 4; ++ni)
                        mma16816(&acc[(mi * 4 + ni) * 4], af[mi], bf[ni]);
            }
        }

        // N-chunk epilogue: +b1, relu, dot W2 -> per-row partials in zs
        const int colg = n0 + warp_n * 32 + (lane & 3) * 2;
        #pragma unroll
        for (int mi = 0; mi < 4; ++mi) {
            float z0 = 0.f, z1 = 0.f;
            #pragma unroll
            for (int ni = 0; ni < 4; ++ni) {
                int c = colg + ni * 8;
                float b1a = b1s[c], b1b = b1s[c + 1];
                float w2a = w2s[c], w2b = w2s[c + 1];
                const float* cc = &acc[(mi * 4 + ni) * 4];
                z0 += fmaxf(cc[0] + b1a, 0.f) * w2a + fmaxf(cc[1] + b1b, 0.f) * w2b;
                z1 += fmaxf(cc[2] + b1a, 0.f) * w2a + fmaxf(cc[3] + b1b, 0.f) * w2b;
            }
            z0 += __shfl_xor_sync(0xffffffffu, z0, 1);
            z0 += __shfl_xor_sync(0xffffffffu, z0, 2);
            z1 += __shfl_xor_sync(0xffffffffu, z1, 1);
            z1 += __shfl_xor_sync(0xffffffffu, z1, 2);
            if ((lane & 3) == 0) {
                int r = warp_m * 64 + mi * 16 + (lane >> 2);
                zs[warp_n * 256 + r]     += z0;
                zs[warp_n * 256 + r + 8] += z1;
            }
        }
    }

    __syncthreads();
    if (tid < 256) {
        float z = zs[tid] + zs[256 + tid] + zs[512 + tid] + zs[768 + tid] + b2[0];
        int t_l = tid >> 4, i_l = tid & 15;
        if (i0 + i_l < ILEN)
            g_gate[((size_t)b * TLEN + t0 + t_l) * ILEN + i0 + i_l] = 1.f / (1.f + expf(-z));
    }
}

// ---------------- repack k -> kT[b][h][d][i] ----------------
__global__ __launch_bounds__(256)
void repack_kT_kernel() {
    int idx = blockIdx.x * 256 + threadIdx.x;
    const int total = BSZ*NHEADS*DH*ILEN;
    if (idx >= total) return;
    int i = idx % ILEN;
    int d = (idx / ILEN) % DH;
    int h = (idx / (ILEN*DH)) % NHEADS;
    int b = idx / (ILEN*DH*NHEADS);
    g_kT[idx] = g_k[(b*ILEN + i)*H + h*DH + d];
}

// ---------------- attention: scores -> softmax -> *gate -> ctx ----------------
__global__ __launch_bounds__(256)
void attn_kernel(float* __restrict__ out) {
    __shared__ float q_s[8][DH];
    __shared__ float p_s[8][ILEN + 3];

    const int w    = threadIdx.x >> 5;
    const int lane = threadIdx.x & 31;
    const int b = blockIdx.z, h = blockIdx.y;
    const int t = blockIdx.x * 8 + w;

    const float* qrow = g_q + (b*TLEN + t)*H + h*DH;
    q_s[w][lane]      = qrow[lane];
    q_s[w][lane + 32] = qrow[lane + 32];
    __syncwarp();

    const float* kT = g_kT + (b*NHEADS + h) * DH * ILEN;
    const float scale = 0.125f;

    float mx = -1e30f;
    for (int c = 0; c < 7; ++c) {
        int i = c*32 + lane;
        float s = -1e30f;
        if (i < ILEN) {
            float a0 = 0.f, a1 = 0.f, a2 = 0.f, a3 = 0.f;
            #pragma unroll
            for (int d = 0; d < DH; d += 4) {
                a0 += q_s[w][d+0] * kT[(d+0)*ILEN + i];
                a1 += q_s[w][d+1] * kT[(d+1)*ILEN + i];
                a2 += q_s[w][d+2] * kT[(d+2)*ILEN + i];
                a3 += q_s[w][d+3] * kT[(d+3)*ILEN + i];
            }
            s = (a0 + a1 + a2 + a3) * scale;
            p_s[w][i] = s;
        }
        mx = fmaxf(mx, s);
    }
    #pragma unroll
    for (int off = 16; off; off >>= 1)
        mx = fmaxf(mx, __shfl_xor_sync(0xffffffffu, mx, off));

    float sm = 0.f;
    for (int c = 0; c < 7; ++c) {
        int i = c*32 + lane;
        if (i < ILEN) {
            float e = expf(p_s[w][i] - mx);
            p_s[w][i] = e;
            sm += e;
        }
    }
    #pragma unroll
    for (int off = 16; off; off >>= 1)
        sm += __shfl_xor_sync(0xffffffffu, sm, off);
    float inv = 1.f / sm;

    const float* gaterow = g_gate + (b*TLEN + t)*ILEN;
    for (int c = 0; c < 7; ++c) {
        int i = c*32 + lane;
        if (i < ILEN) p_s[w][i] *= inv * gaterow[i];
    }
    __syncwarp();

    float c0 = 0.f, c1 = 0.f;
    const float* vbase = g_v + b*ILEN*H + h*DH;
    for (int i = 0; i < ILEN; ++i) {
        float p = p_s[w][i];
        c0 += p * vbase[i*H + lane];
        c1 += p * vbase[i*H + lane + 32];
    }
    float* orow = out + (b*TLEN + t)*H + h*DH;
    orow[lane]      = c0;
    orow[lane + 32] = c1;
}

// ---------------- launch ----------------
extern "C" void kernel_launch(void* const* d_in, const int* in_sizes, int n_in,
                              void* d_out, int out_size) {
    const float* text  = (const float*)d_in[0];
    const float* image = (const float*)d_in[1];
    const float* Wq = (const float*)d_in[2];  const float* bq = (const float*)d_in[3];
    const float* Wk = (const float*)d_in[4];  const float* bk = (const float*)d_in[5];
    const float* Wv = (const float*)d_in[6];  const float* bv = (const float*)d_in[7];
    const float* Wt = (const float*)d_in[8];  const float* bt = (const float*)d_in[9];
    const float* Wi = (const float*)d_in[10]; const float* bi = (const float*)d_in[11];
    const float* W1 = (const float*)d_in[12]; const float* b1 = (const float*)d_in[13];
    const float* W2 = (const float*)d_in[14]; const float* b2 = (const float*)d_in[15];
    float* out = (float*)d_out;

    cudaFuncSetAttribute(proj_kernel, cudaFuncAttributeMaxDynamicSharedMemorySize, PJ_SMEM);
    cudaFuncSetAttribute(gate_kernel, cudaFuncAttributeMaxDynamicSharedMemorySize, GT_SMEM);

    prep_weights<<<dim3(24, 24, 6), 256>>>(Wt, Wq, Wi, Wk, Wv, W1);
    proj_kernel<<<dim3(6, 13, 5), 256, PJ_SMEM>>>(text, image, bt, bq, bi, bk, bv);
    repack_kT_kernel<<<(BSZ*NHEADS*DH*ILEN + 255)/256, 256>>>();
    gate_kernel<<<dim3(13, 4, 8), 512, GT_SMEM>>>(b1, W2, b2);
    attn_kernel<<<dim3(TLEN/8, NHEADS, BSZ), 256>>>(out);
}